// round 14
// baseline (speedup 1.0000x reference)
#include <cuda_runtime.h>
#include <cuda_fp16.h>
#include <cstdint>

// Problem constants
#define NB    32
#define CIN   256
#define COUT  256
#define TT    128
#define VV    25
#define KK    3
#define KCOUT 768
#define TVN   3200         // T*V
#define NTV   102400       // N*T*V
#define BN_EPS 1e-5f
#define NSLOT 16

#define NTHR  384          // 12 warps: 3M x 4N

// Device-global scratch (allocation-free per harness rules)
__device__ __half g_yo[(size_t)NB * COUT * TVN];    // pre-BN output, fp16, 52 MB
__device__ __half g_Wh[KCOUT * CIN];                // fp16 W, rows o' = c*3+k
__device__ __half g_xh[(size_t)NB * TVN * CIN];     // fp16 x transposed [n][tv][ci], 52 MB
__device__ float  g_sum2[NSLOT * COUT];
__device__ float  g_sq2 [NSLOT * COUT];
__device__ float  g_scale[COUT];
__device__ float  g_shift[COUT];

// ---------------------------------------------------------------------------
__device__ __forceinline__ uint32_t smem_u32(const void* p) {
    return (uint32_t)__cvta_generic_to_shared(p);
}
__device__ __forceinline__ void cp16(uint32_t dst, const void* src) {
    asm volatile("cp.async.cg.shared.global [%0], [%1], 16;" :: "r"(dst), "l"(src));
}
__device__ __forceinline__ void ldsm_x4(uint32_t& r0, uint32_t& r1, uint32_t& r2, uint32_t& r3,
                                        uint32_t addr) {
    asm volatile("ldmatrix.sync.aligned.m8n8.x4.shared.b16 {%0,%1,%2,%3}, [%4];"
                 : "=r"(r0), "=r"(r1), "=r"(r2), "=r"(r3) : "r"(addr));
}
// fp16 mma, fp32 accumulate (epilogue contraction)
__device__ __forceinline__ void mma_f16(float c[4], const uint32_t a[4], uint32_t b0, uint32_t b1) {
    asm volatile(
        "mma.sync.aligned.m16n8k16.row.col.f32.f16.f16.f32 "
        "{%0,%1,%2,%3}, {%4,%5,%6,%7}, {%8,%9}, {%0,%1,%2,%3};\n"
        : "+f"(c[0]), "+f"(c[1]), "+f"(c[2]), "+f"(c[3])
        : "r"(a[0]), "r"(a[1]), "r"(a[2]), "r"(a[3]), "r"(b0), "r"(b1));
}
// fp16 mma, fp16 accumulate (mainloop — potential 2x rate)
__device__ __forceinline__ void mma_f16acc(uint32_t c[2], const uint32_t a[4],
                                           uint32_t b0, uint32_t b1) {
    asm volatile(
        "mma.sync.aligned.m16n8k16.row.col.f16.f16.f16.f16 "
        "{%0,%1}, {%2,%3,%4,%5}, {%6,%7}, {%0,%1};\n"
        : "+r"(c[0]), "+r"(c[1])
        : "r"(a[0]), "r"(a[1]), "r"(a[2]), "r"(a[3]), "r"(b0), "r"(b1));
}

// ---------------------------------------------------------------------------
// Prep kernels
// ---------------------------------------------------------------------------
// W[(k*256+c)*256+ci] -> g_Wh[(c*3+k)*256+ci] fp16; first 16 blocks also zero stats
__global__ void convW_kernel(const float* __restrict__ W) {
    int op = blockIdx.x;          // 0..767 = c*3+k
    int ci = threadIdx.x;
    if (op < NSLOT * COUT / 256) {             // 16 blocks x 256 = 4096 slots
        g_sum2[op * 256 + ci] = 0.0f;
        g_sq2 [op * 256 + ci] = 0.0f;
    }
    int c = op / 3, k = op % 3;
    g_Wh[op * CIN + ci] = __float2half(W[(k * COUT + c) * CIN + ci]);
}

// x[n][ci][tv] fp32 -> g_xh[n][tv][ci] fp16
__global__ __launch_bounds__(256) void transpose_kernel(const float* __restrict__ x) {
    __shared__ float tile[64][33];
    const int tv0 = blockIdx.x * 32;     // 100
    const int ci0 = blockIdx.y * 64;     // 4
    const int n   = blockIdx.z;          // 32
    const int tid = threadIdx.x;
    {
        const int tvl = tid & 31, cl = tid >> 5;   // (32, 8)
        const float* xs = x + (size_t)n * CIN * TVN + tv0 + tvl;
        #pragma unroll
        for (int it = 0; it < 8; it++) {
            int ci = cl + 8 * it;
            tile[ci][tvl] = xs[(size_t)(ci0 + ci) * TVN];
        }
    }
    __syncthreads();
    {
        const int cil = tid & 63, tl = tid >> 6;   // (64, 4)
        __half* od = g_xh + ((size_t)n * TVN + tv0) * CIN + ci0 + cil;
        #pragma unroll
        for (int it = 0; it < 8; it++) {
            int tv = tl + 4 * it;
            od[(size_t)tv * CIN] = __float2half(tile[cil][tv]);
        }
    }
}

// ---------------------------------------------------------------------------
// Fused kernel: M=96, N=200 (8 t), K=256 kstep=64, 4-stage cp.async,
// 12 warps (3M x 4N). Mainloop: fp16-acc HMMA chained over K=32, spilled
// to fp32. Epilogue: fp16 mma contraction over packed kv=k*25+v.
// ---------------------------------------------------------------------------
#define STGA 12288               // 96 rows x 128 B
#define STGB 25600               // 200 rows x 128 B
#define STG  (STGA + STGB)       // 37888 B / stage
#define NSTG 4
#define DYN_BYTES (NSTG * STG)   // 151552 B
// epilogue aliases (halves): y1h [32c][8t][80kv] = 20480 halves (40960 B),
// y2s [32c][200] halves at +40960 B

__global__ __launch_bounds__(NTHR, 1) void fused_kernel(
    const float* __restrict__ A, const float* __restrict__ bias)
{
    extern __shared__ __align__(16) char dyn[];
    const uint32_t sbu = smem_u32(dyn);
    __half* y1h = (__half*)dyn;                      // [c][t][kv] epilogue alias
    __half* y2s = (__half*)(dyn + 40960);            // [32][200]

    __shared__ __half AhT[32 * 80];    // [w][kv] fp16 adjacency, kv=k*25+v, zero-padded
    __shared__ float biass[96];

    const int tid  = threadIdx.x;
    const int lane = tid & 31;
    const int warp = tid >> 5;
    const int wm   = warp >> 2;      // 0..2  (32 M-rows each)
    const int wn   = warp & 3;       // 0..3
    const int g    = lane >> 2;
    const int k4   = lane & 3;
    const int la7  = lane & 7;
    const int la8  = (lane >> 3) & 1;
    const int la16 = (lane >> 4) & 1;
    const int q    = lane >> 3;

    const int m0     = blockIdx.x * 96;      // 8 M tiles
    const int c0     = blockIdx.x * 32;
    const int ct     = blockIdx.y;           // 512 column tiles
    const int n      = ct >> 4;
    const int tvbase = (ct & 15) * 200;
    const int slot   = ct & (NSLOT - 1);

    // static smem fills (consumed after later syncs)
    for (int i = tid; i < 32 * 80; i += NTHR) {
        int w = i / 80, kv = i % 80;
        __half val = __float2half(0.0f);
        if (w < VV && kv < KK * VV) {
            int k = kv / VV, v = kv % VV;
            val = __float2half(A[(k * VV + v) * VV + w]);
        }
        AhT[i] = val;
    }
    if (tid < 96) {
        int op = m0 + tid;
        biass[tid] = bias[(op % 3) * COUT + (op / 3)];
    }

    // Per-warp fragment address precompute (kk16 enters only via swizzle XOR)
    uint32_t aOff[2], aLow[2], bOff[4], bLow[4];
    #pragma unroll
    for (int mi = 0; mi < 2; mi++) {
        int row = wm * 32 + mi * 16 + la7 + la8 * 8;
        aOff[mi] = row * 128;
        aLow[mi] = row & 7;
    }
    #pragma unroll
    for (int p4 = 0; p4 < 4; p4++) {
        int jq = (q < 2) ? (wn + 8 * p4) : (wn + 8 * p4 + 4);
        if (jq > 24) jq = 24;                // clamp (results unused)
        int row = jq * 8 + la7;
        bOff[p4] = row * 128;
        bLow[p4] = row & 7;
    }

    float acc[2][7][4];
    #pragma unroll
    for (int mi = 0; mi < 2; mi++)
        #pragma unroll
        for (int i = 0; i < 7; i++)
            #pragma unroll
            for (int r = 0; r < 4; r++) acc[mi][i][r] = 0.0f;

    // ---- stage loader ----
    auto issue = [&](int s) {
        const int kk = s * 64;
        const uint32_t stb = sbu + (uint32_t)(s & (NSTG - 1)) * STG;
        #pragma unroll
        for (int p = 0; p < 2; p++) {              // 768 chunks of W tile
            int i = tid + p * NTHR;
            int row = i >> 3, ch = i & 7;
            uint32_t dst = stb + row * 128 + (uint32_t)((ch ^ (row & 7)) << 4);
            cp16(dst, g_Wh + (size_t)(m0 + row) * CIN + kk + ch * 8);
        }
        #pragma unroll
        for (int p = 0; p < 5; p++) {              // 1600 chunks of x tile
            int i = tid + p * NTHR;
            if (i < 1600) {
                int row = i >> 3, ch = i & 7;
                uint32_t dst = stb + STGA + row * 128 + (uint32_t)((ch ^ (row & 7)) << 4);
                cp16(dst, g_xh + ((size_t)n * TVN + tvbase + row) * CIN + kk + ch * 8);
            }
        }
        asm volatile("cp.async.commit_group;" ::: "memory");
    };

    issue(0); issue(1); issue(2);

    uint32_t afr[2][4], bfr[8][2];             // single-buffered fragments
    uint32_t acc16[2][7][2];                   // fp16 partial accumulators (K=32 window)

    auto ldfrag = [&](uint32_t Asb, uint32_t Bsb, int kk16) {
        #pragma unroll
        for (int mi = 0; mi < 2; mi++) {
            uint32_t ch = (uint32_t)(kk16 * 2 + la16) ^ aLow[mi];
            ldsm_x4(afr[mi][0], afr[mi][1], afr[mi][2], afr[mi][3],
                    Asb + aOff[mi] + (ch << 4));
        }
        #pragma unroll
        for (int p4 = 0; p4 < 4; p4++) {
            uint32_t ch = (uint32_t)(kk16 * 2 + (q & 1)) ^ bLow[p4];
            uint32_t r0, r1, r2, r3;
            ldsm_x4(r0, r1, r2, r3, Bsb + bOff[p4] + (ch << 4));
            bfr[2 * p4][0] = r0;     bfr[2 * p4][1] = r1;
            bfr[2 * p4 + 1][0] = r2; bfr[2 * p4 + 1][1] = r3;
        }
    };

    for (int s = 0; s < 4; s++) {
        if (s == 0 || s == 1) asm volatile("cp.async.wait_group 2;" ::: "memory");
        else if (s == 2)      asm volatile("cp.async.wait_group 1;" ::: "memory");
        else                  asm volatile("cp.async.wait_group 0;" ::: "memory");
        __syncthreads();
        if (s + 3 < 4) issue(s + 3);

        const uint32_t Asb = sbu + (uint32_t)(s & (NSTG - 1)) * STG;
        const uint32_t Bsb = Asb + STGA;

        #pragma unroll
        for (int kk16 = 0; kk16 < 4; kk16++) {
            ldfrag(Asb, Bsb, kk16);
            if ((kk16 & 1) == 0) {
                #pragma unroll
                for (int mi = 0; mi < 2; mi++)
                    #pragma unroll
                    for (int i = 0; i < 7; i++) {
                        acc16[mi][i][0] = 0u; acc16[mi][i][1] = 0u;
                    }
            }
            #pragma unroll
            for (int mi = 0; mi < 2; mi++)
                #pragma unroll
                for (int i = 0; i < 7; i++)
                    if (wn + 4 * i < 25)
                        mma_f16acc(acc16[mi][i], afr[mi], bfr[i][0], bfr[i][1]);
            if (kk16 & 1) {
                // spill fp16 K=32 partials into fp32 accumulators
                #pragma unroll
                for (int mi = 0; mi < 2; mi++)
                    #pragma unroll
                    for (int i = 0; i < 7; i++) {
                        if (wn + 4 * i < 25) {
                            float2 lo = __half22float2(*(__half2*)&acc16[mi][i][0]);
                            float2 hi = __half22float2(*(__half2*)&acc16[mi][i][1]);
                            acc[mi][i][0] += lo.x; acc[mi][i][1] += lo.y;
                            acc[mi][i][2] += hi.x; acc[mi][i][3] += hi.y;
                        }
                    }
            }
        }
    }

    // ---------------- epilogue ----------------
    __syncthreads();   // mainloop smem reads complete; safe to alias

    // 1) accs (+bias) -> y1h fp16 [c][t][kv = k*25+v]; also zero kv pads 75..79
    #pragma unroll
    for (int mi = 0; mi < 2; mi++) {
        #pragma unroll
        for (int h = 0; h < 2; h++) {
            const int row  = wm * 32 + mi * 16 + h * 8 + g;
            const int crow = row / 3, kr = row % 3;
            const float bv = biass[row];
            #pragma unroll
            for (int i = 0; i < 7; i++) {
                int j = wn + 4 * i;
                if (j < 25) {
                    #pragma unroll
                    for (int p = 0; p < 2; p++) {
                        int col = j * 8 + k4 * 2 + p;
                        int t2 = col / 25, v = col % 25;
                        y1h[crow * 640 + t2 * 80 + kr * 25 + v] =
                            __float2half(acc[mi][i][h * 2 + p] + bv);
                    }
                }
            }
        }
    }
    for (int i = tid; i < 32 * 8 * 5; i += NTHR) {        // zero kv 75..79
        int c = i / 40, rem = i % 40;
        y1h[c * 640 + (rem / 5) * 80 + 75 + (rem % 5)] = __float2half(0.0f);
    }
    __syncthreads();

    // 2) per-warp (t = warp, warps 0-7) fp16 mma contraction:
    //    D[32c][32w] = y1h[c][kv] @ AhT^T[kv][w], kv = 80 (5 k16 steps)
    if (warp < 8) {
        const int t = warp;
        float acc2[2][4][4];
        #pragma unroll
        for (int mi = 0; mi < 2; mi++)
            #pragma unroll
            for (int nj = 0; nj < 4; nj++)
                #pragma unroll
                for (int r = 0; r < 4; r++) acc2[mi][nj][r] = 0.0f;

        #pragma unroll
        for (int st = 0; st < 5; st++) {
            const int kvb = st * 16;
            uint32_t a[2][4], b[4][2];
            #pragma unroll
            for (int mi = 0; mi < 2; mi++) {
                const int r0 = (mi * 16 + g) * 640 + t * 80 + kvb + 2 * k4;
                a[mi][0] = *(const uint32_t*)&y1h[r0];
                a[mi][1] = *(const uint32_t*)&y1h[r0 + 8 * 640];
                a[mi][2] = *(const uint32_t*)&y1h[r0 + 8];
                a[mi][3] = *(const uint32_t*)&y1h[r0 + 8 * 640 + 8];
            }
            #pragma unroll
            for (int nj = 0; nj < 4; nj++) {
                const int wb = (nj * 8 + g) * 80 + kvb + 2 * k4;
                b[nj][0] = *(const uint32_t*)&AhT[wb];
                b[nj][1] = *(const uint32_t*)&AhT[wb + 8];
            }
            #pragma unroll
            for (int mi = 0; mi < 2; mi++)
                #pragma unroll
                for (int nj = 0; nj < 4; nj++)
                    mma_f16(acc2[mi][nj], a[mi], b[nj][0], b[nj][1]);
        }

        // 3) store contraction result -> y2s fp16 [32c][200] (scalar stores)
        #pragma unroll
        for (int mi = 0; mi < 2; mi++) {
            #pragma unroll
            for (int h = 0; h < 2; h++) {
                const int c = mi * 16 + h * 8 + g;
                #pragma unroll
                for (int nj = 0; nj < 4; nj++) {
                    const int wcol = nj * 8 + k4 * 2;
                    if (wcol < VV)
                        y2s[c * 200 + t * 25 + wcol]     = __float2half(acc2[mi][nj][h * 2 + 0]);
                    if (wcol + 1 < VV)
                        y2s[c * 200 + t * 25 + wcol + 1] = __float2half(acc2[mi][nj][h * 2 + 1]);
                }
            }
        }
    }
    __syncthreads();

    // 4) BN partial stats from quantized y2 (first 256 threads: 32 c x 8 t)
    if (tid < 256) {
        const int cl = tid >> 3, tl = tid & 7;
        float s = 0.0f, s2 = 0.0f;
        #pragma unroll
        for (int v = 0; v < VV; v++) {
            float val = __half2float(y2s[cl * 200 + tl * 25 + v]);
            s += val; s2 += val * val;
        }
        s  += __shfl_down_sync(0xFFFFFFFFu, s,  4, 8);
        s2 += __shfl_down_sync(0xFFFFFFFFu, s2, 4, 8);
        s  += __shfl_down_sync(0xFFFFFFFFu, s,  2, 8);
        s2 += __shfl_down_sync(0xFFFFFFFFu, s2, 2, 8);
        s  += __shfl_down_sync(0xFFFFFFFFu, s,  1, 8);
        s2 += __shfl_down_sync(0xFFFFFFFFu, s2, 1, 8);
        if ((tid & 7) == 0) {
            atomicAdd(&g_sum2[slot * COUT + c0 + cl], s);
            atomicAdd(&g_sq2 [slot * COUT + c0 + cl], s2);
        }
    }

    // 5) coalesced copy y2s -> g_yo: 32 rows x 25 uint4 (8 halves) = full 200 cols
    {
        const size_t base = ((size_t)n * COUT + c0) * TVN + tvbase;   // half index, 16B-aligned
        const uint4* src = (const uint4*)y2s;                          // row stride 25 uint4
        uint4* dst = (uint4*)(g_yo + base);                            // row stride TVN/8 uint4
        #pragma unroll
        for (int p = 0; p < 3; p++) {
            int i = tid + p * NTHR;
            if (i < 800) {
                int row = i / 25, q4 = i % 25;
                dst[(size_t)row * (TVN / 8) + q4] = src[row * 25 + q4];
            }
        }
    }
}

// ---------------------------------------------------------------------------
__global__ void finalize_kernel(const float* __restrict__ gamma, const float* __restrict__ beta) {
    int c = threadIdx.x;
    float s = 0.0f, s2 = 0.0f;
    #pragma unroll
    for (int sl = 0; sl < NSLOT; sl++) {
        s  += g_sum2[sl * COUT + c];
        s2 += g_sq2 [sl * COUT + c];
    }
    const float inv_n = 1.0f / (float)NTV;
    const float mu  = s * inv_n;
    const float var = s2 * inv_n - mu * mu;
    const float rin = rsqrtf(var + BN_EPS);
    const float sc  = gamma[c] * rin;
    g_scale[c] = sc;
    g_shift[c] = beta[c] - mu * sc;
}

// normalize + ReLU: fp16 in, fp32 out, 8 elements/thread
__global__ __launch_bounds__(256) void bn_kernel(float* __restrict__ out)
{
    const size_t i  = (size_t)blockIdx.x * 256 + threadIdx.x;   // uint4 (8-half) index
    const size_t h0 = i * 8;
    const int c = (int)((h0 / TVN) % COUT);                     // 8 | TVN -> uniform
    const float sc = g_scale[c];
    const float sh = g_shift[c];
    uint4 raw = ((const uint4*)g_yo)[i];
    float4 o0, o1;
    {
        __half2 p = *(__half2*)&raw.x; float2 f = __half22float2(p);
        o0.x = fmaxf(f.x * sc + sh, 0.0f); o0.y = fmaxf(f.y * sc + sh, 0.0f);
        p = *(__half2*)&raw.y; f = __half22float2(p);
        o0.z = fmaxf(f.x * sc + sh, 0.0f); o0.w = fmaxf(f.y * sc + sh, 0.0f);
        p = *(__half2*)&raw.z; f = __half22float2(p);
        o1.x = fmaxf(f.x * sc + sh, 0.0f); o1.y = fmaxf(f.y * sc + sh, 0.0f);
        p = *(__half2*)&raw.w; f = __half22float2(p);
        o1.z = fmaxf(f.x * sc + sh, 0.0f); o1.w = fmaxf(f.y * sc + sh, 0.0f);
    }
    ((float4*)out)[i * 2]     = o0;
    ((float4*)out)[i * 2 + 1] = o1;
}

// ---------------------------------------------------------------------------
extern "C" void kernel_launch(void* const* d_in, const int* in_sizes, int n_in,
                              void* d_out, int out_size)
{
    const float* x     = (const float*)d_in[0];   // [32,256,128,25]
    const float* A     = (const float*)d_in[1];   // [3,25,25]
    const float* W     = (const float*)d_in[2];   // [768,256]
    const float* b     = (const float*)d_in[3];   // [768]
    const float* gamma = (const float*)d_in[4];   // [256]
    const float* beta  = (const float*)d_in[5];   // [256]

    cudaFuncSetAttribute(fused_kernel, cudaFuncAttributeMaxDynamicSharedMemorySize, DYN_BYTES);

    convW_kernel<<<KCOUT, CIN>>>(W);              // also zeroes BN stat slots

    dim3 tg(100, 4, 32);
    transpose_kernel<<<tg, 256>>>(x);

    dim3 grid(8, 512);   // M tiles fastest -> blocks sharing x tiles run adjacently
    fused_kernel<<<grid, NTHR, DYN_BYTES>>>(A, b);

    finalize_kernel<<<1, COUT>>>(gamma, beta);

    const int nblk = (NB * COUT * TVN) / 8 / 256;   // 12800
    bn_kernel<<<nblk, 256>>>((float*)d_out);
}

// round 15
// speedup vs baseline: 1.0909x; 1.0909x over previous
#include <cuda_runtime.h>
#include <cuda_fp16.h>
#include <cstdint>

// Problem constants
#define NB    32
#define CIN   256
#define COUT  256
#define TT    128
#define VV    25
#define KK    3
#define KCOUT 768
#define TVN   3200         // T*V
#define NTV   102400       // N*T*V
#define BN_EPS 1e-5f
#define NSLOT 16

#define NTHR  384          // 12 warps: 3M x 4N

// Device-global scratch (allocation-free per harness rules)
__device__ __half g_yo[(size_t)NB * COUT * TVN];    // pre-BN output, fp16, 52 MB
__device__ __half g_Wh[KCOUT * CIN];                // fp16 W, rows o' = c*3+k
__device__ __half g_xh[(size_t)NB * TVN * CIN];     // fp16 x transposed [n][tv][ci], 52 MB
__device__ float  g_sum2[NSLOT * COUT];
__device__ float  g_sq2 [NSLOT * COUT];

// ---------------------------------------------------------------------------
__device__ __forceinline__ uint32_t smem_u32(const void* p) {
    return (uint32_t)__cvta_generic_to_shared(p);
}
__device__ __forceinline__ void cp16(uint32_t dst, const void* src) {
    asm volatile("cp.async.cg.shared.global [%0], [%1], 16;" :: "r"(dst), "l"(src));
}
__device__ __forceinline__ void ldsm_x4(uint32_t& r0, uint32_t& r1, uint32_t& r2, uint32_t& r3,
                                        uint32_t addr) {
    asm volatile("ldmatrix.sync.aligned.m8n8.x4.shared.b16 {%0,%1,%2,%3}, [%4];"
                 : "=r"(r0), "=r"(r1), "=r"(r2), "=r"(r3) : "r"(addr));
}
// fp16 mma, fp32 accumulate
__device__ __forceinline__ void mma_f16(float c[4], const uint32_t a[4], uint32_t b0, uint32_t b1) {
    asm volatile(
        "mma.sync.aligned.m16n8k16.row.col.f32.f16.f16.f32 "
        "{%0,%1,%2,%3}, {%4,%5,%6,%7}, {%8,%9}, {%0,%1,%2,%3};\n"
        : "+f"(c[0]), "+f"(c[1]), "+f"(c[2]), "+f"(c[3])
        : "r"(a[0]), "r"(a[1]), "r"(a[2]), "r"(a[3]), "r"(b0), "r"(b1));
}

// ---------------------------------------------------------------------------
// Prep kernel: x transpose+convert; first blocks also convert W and zero stats
// ---------------------------------------------------------------------------
__global__ __launch_bounds__(256) void transpose_kernel(
    const float* __restrict__ x, const float* __restrict__ W)
{
    __shared__ float tile[64][33];
    const int tv0 = blockIdx.x * 32;     // 100
    const int ci0 = blockIdx.y * 64;     // 4
    const int n   = blockIdx.z;          // 32
    const int tid = threadIdx.x;

    // Side duties for the first flattened blocks (independent of tile work)
    const int bid = blockIdx.x + 100 * (blockIdx.y + 4 * blockIdx.z);
    if (bid < KCOUT) {                    // convert one W row: op = c*3+k
        int c = bid / 3, k = bid % 3;
        g_Wh[bid * CIN + tid] = __float2half(W[(k * COUT + c) * CIN + tid]);
    } else if (bid < KCOUT + NSLOT) {     // zero BN stat slots
        int i = (bid - KCOUT) * 256 + tid;
        g_sum2[i] = 0.0f;
        g_sq2 [i] = 0.0f;
    }

    {
        const int tvl = tid & 31, cl = tid >> 5;   // (32, 8)
        const float* xs = x + (size_t)n * CIN * TVN + tv0 + tvl;
        #pragma unroll
        for (int it = 0; it < 8; it++) {
            int ci = cl + 8 * it;
            tile[ci][tvl] = xs[(size_t)(ci0 + ci) * TVN];
        }
    }
    __syncthreads();
    {
        const int cil = tid & 63, tl = tid >> 6;   // (64, 4)
        __half* od = g_xh + ((size_t)n * TVN + tv0) * CIN + ci0 + cil;
        #pragma unroll
        for (int it = 0; it < 8; it++) {
            int tv = tl + 4 * it;
            od[(size_t)tv * CIN] = __float2half(tile[cil][tv]);
        }
    }
}

// ---------------------------------------------------------------------------
// Fused kernel: M=96, N=200 (8 t), K=256 kstep=64, 4-stage cp.async,
// 12 warps (3M x 4N), fragment double-buffer (R13-proven mainloop).
// Epilogue: fp16 mma contraction over packed kv=k*25+v.
// ---------------------------------------------------------------------------
#define STGA 12288               // 96 rows x 128 B
#define STGB 25600               // 200 rows x 128 B
#define STG  (STGA + STGB)       // 37888 B / stage
#define NSTG 4
#define DYN_BYTES (NSTG * STG)   // 151552 B
// epilogue aliases (halves): y1h [32c][8t][80kv] = 20480 halves (40960 B),
// y2s [32c][200] halves at +40960 B

__global__ __launch_bounds__(NTHR, 1) void fused_kernel(
    const float* __restrict__ A, const float* __restrict__ bias)
{
    extern __shared__ __align__(16) char dyn[];
    const uint32_t sbu = smem_u32(dyn);
    __half* y1h = (__half*)dyn;                      // [c][t][kv] epilogue alias
    __half* y2s = (__half*)(dyn + 40960);            // [32][200]

    __shared__ __half AhT[32 * 80];    // [w][kv] fp16 adjacency, kv=k*25+v, zero-padded
    __shared__ float biass[96];

    const int tid  = threadIdx.x;
    const int lane = tid & 31;
    const int warp = tid >> 5;
    const int wm   = warp >> 2;      // 0..2  (32 M-rows each)
    const int wn   = warp & 3;       // 0..3
    const int g    = lane >> 2;
    const int k4   = lane & 3;
    const int la7  = lane & 7;
    const int la8  = (lane >> 3) & 1;
    const int la16 = (lane >> 4) & 1;
    const int q    = lane >> 3;

    const int m0     = blockIdx.x * 96;      // 8 M tiles
    const int c0     = blockIdx.x * 32;
    const int ct     = blockIdx.y;           // 512 column tiles
    const int n      = ct >> 4;
    const int tvbase = (ct & 15) * 200;
    const int slot   = ct & (NSLOT - 1);

    // static smem fills (consumed after later syncs)
    for (int i = tid; i < 32 * 80; i += NTHR) {
        int w = i / 80, kv = i % 80;
        __half val = __float2half(0.0f);
        if (w < VV && kv < KK * VV) {
            int k = kv / VV, v = kv % VV;
            val = __float2half(A[(k * VV + v) * VV + w]);
        }
        AhT[i] = val;
    }
    if (tid < 96) {
        int op = m0 + tid;
        biass[tid] = bias[(op % 3) * COUT + (op / 3)];
    }

    // Per-warp fragment address precompute (kk16 enters only via swizzle XOR)
    uint32_t aOff[2], aLow[2], bOff[4], bLow[4];
    #pragma unroll
    for (int mi = 0; mi < 2; mi++) {
        int row = wm * 32 + mi * 16 + la7 + la8 * 8;
        aOff[mi] = row * 128;
        aLow[mi] = row & 7;
    }
    #pragma unroll
    for (int p4 = 0; p4 < 4; p4++) {
        int jq = (q < 2) ? (wn + 8 * p4) : (wn + 8 * p4 + 4);
        if (jq > 24) jq = 24;                // clamp (results unused)
        int row = jq * 8 + la7;
        bOff[p4] = row * 128;
        bLow[p4] = row & 7;
    }

    float acc[2][7][4];
    #pragma unroll
    for (int mi = 0; mi < 2; mi++)
        #pragma unroll
        for (int i = 0; i < 7; i++)
            #pragma unroll
            for (int r = 0; r < 4; r++) acc[mi][i][r] = 0.0f;

    // ---- stage loader ----
    auto issue = [&](int s) {
        const int kk = s * 64;
        const uint32_t stb = sbu + (uint32_t)(s & (NSTG - 1)) * STG;
        #pragma unroll
        for (int p = 0; p < 2; p++) {              // 768 chunks of W tile
            int i = tid + p * NTHR;
            int row = i >> 3, ch = i & 7;
            uint32_t dst = stb + row * 128 + (uint32_t)((ch ^ (row & 7)) << 4);
            cp16(dst, g_Wh + (size_t)(m0 + row) * CIN + kk + ch * 8);
        }
        #pragma unroll
        for (int p = 0; p < 5; p++) {              // 1600 chunks of x tile
            int i = tid + p * NTHR;
            if (i < 1600) {
                int row = i >> 3, ch = i & 7;
                uint32_t dst = stb + STGA + row * 128 + (uint32_t)((ch ^ (row & 7)) << 4);
                cp16(dst, g_xh + ((size_t)n * TVN + tvbase + row) * CIN + kk + ch * 8);
            }
        }
        asm volatile("cp.async.commit_group;" ::: "memory");
    };

    issue(0); issue(1); issue(2);

    uint32_t afr[2][2][4], bfr[2][8][2];       // double-buffered fragments

    auto ldfrag = [&](int buf, uint32_t Asb, uint32_t Bsb, int kk16) {
        #pragma unroll
        for (int mi = 0; mi < 2; mi++) {
            uint32_t ch = (uint32_t)(kk16 * 2 + la16) ^ aLow[mi];
            ldsm_x4(afr[buf][mi][0], afr[buf][mi][1], afr[buf][mi][2], afr[buf][mi][3],
                    Asb + aOff[mi] + (ch << 4));
        }
        #pragma unroll
        for (int p4 = 0; p4 < 4; p4++) {
            uint32_t ch = (uint32_t)(kk16 * 2 + (q & 1)) ^ bLow[p4];
            uint32_t r0, r1, r2, r3;
            ldsm_x4(r0, r1, r2, r3, Bsb + bOff[p4] + (ch << 4));
            bfr[buf][2 * p4][0] = r0;     bfr[buf][2 * p4][1] = r1;
            bfr[buf][2 * p4 + 1][0] = r2; bfr[buf][2 * p4 + 1][1] = r3;
        }
    };

    for (int s = 0; s < 4; s++) {
        if (s == 0 || s == 1) asm volatile("cp.async.wait_group 2;" ::: "memory");
        else if (s == 2)      asm volatile("cp.async.wait_group 1;" ::: "memory");
        else                  asm volatile("cp.async.wait_group 0;" ::: "memory");
        __syncthreads();
        if (s + 3 < 4) issue(s + 3);

        const uint32_t Asb = sbu + (uint32_t)(s & (NSTG - 1)) * STG;
        const uint32_t Bsb = Asb + STGA;

        ldfrag(0, Asb, Bsb, 0);
        #pragma unroll
        for (int kk16 = 0; kk16 < 4; kk16++) {
            const int cur = kk16 & 1;
            if (kk16 < 3) ldfrag(cur ^ 1, Asb, Bsb, kk16 + 1);
            #pragma unroll
            for (int mi = 0; mi < 2; mi++)
                #pragma unroll
                for (int i = 0; i < 7; i++)
                    if (wn + 4 * i < 25)
                        mma_f16(acc[mi][i], afr[cur][mi], bfr[cur][i][0], bfr[cur][i][1]);
        }
    }

    // ---------------- epilogue ----------------
    __syncthreads();   // mainloop smem reads complete; safe to alias

    // 1) accs (+bias) -> y1h fp16 [c][t][kv = k*25+v]; also zero kv pads 75..79
    #pragma unroll
    for (int mi = 0; mi < 2; mi++) {
        #pragma unroll
        for (int h = 0; h < 2; h++) {
            const int row  = wm * 32 + mi * 16 + h * 8 + g;
            const int crow = row / 3, kr = row % 3;
            const float bv = biass[row];
            #pragma unroll
            for (int i = 0; i < 7; i++) {
                int j = wn + 4 * i;
                if (j < 25) {
                    #pragma unroll
                    for (int p = 0; p < 2; p++) {
                        int col = j * 8 + k4 * 2 + p;
                        int t2 = col / 25, v = col % 25;
                        y1h[crow * 640 + t2 * 80 + kr * 25 + v] =
                            __float2half(acc[mi][i][h * 2 + p] + bv);
                    }
                }
            }
        }
    }
    for (int i = tid; i < 32 * 8 * 5; i += NTHR) {        // zero kv 75..79
        int c = i / 40, rem = i % 40;
        y1h[c * 640 + (rem / 5) * 80 + 75 + (rem % 5)] = __float2half(0.0f);
    }
    __syncthreads();

    // 2) per-warp (t = warp, warps 0-7) fp16 mma contraction:
    //    D[32c][32w] = y1h[c][kv] @ AhT^T[kv][w], kv = 80 (5 k16 steps)
    if (warp < 8) {
        const int t = warp;
        float acc2[2][4][4];
        #pragma unroll
        for (int mi = 0; mi < 2; mi++)
            #pragma unroll
            for (int nj = 0; nj < 4; nj++)
                #pragma unroll
                for (int r = 0; r < 4; r++) acc2[mi][nj][r] = 0.0f;

        #pragma unroll
        for (int st = 0; st < 5; st++) {
            const int kvb = st * 16;
            uint32_t a[2][4], b[4][2];
            #pragma unroll
            for (int mi = 0; mi < 2; mi++) {
                const int r0 = (mi * 16 + g) * 640 + t * 80 + kvb + 2 * k4;
                a[mi][0] = *(const uint32_t*)&y1h[r0];
                a[mi][1] = *(const uint32_t*)&y1h[r0 + 8 * 640];
                a[mi][2] = *(const uint32_t*)&y1h[r0 + 8];
                a[mi][3] = *(const uint32_t*)&y1h[r0 + 8 * 640 + 8];
            }
            #pragma unroll
            for (int nj = 0; nj < 4; nj++) {
                const int wb = (nj * 8 + g) * 80 + kvb + 2 * k4;
                b[nj][0] = *(const uint32_t*)&AhT[wb];
                b[nj][1] = *(const uint32_t*)&AhT[wb + 8];
            }
            #pragma unroll
            for (int mi = 0; mi < 2; mi++)
                #pragma unroll
                for (int nj = 0; nj < 4; nj++)
                    mma_f16(acc2[mi][nj], a[mi], b[nj][0], b[nj][1]);
        }

        // 3) store contraction result -> y2s fp16 [32c][200] (scalar stores)
        #pragma unroll
        for (int mi = 0; mi < 2; mi++) {
            #pragma unroll
            for (int h = 0; h < 2; h++) {
                const int c = mi * 16 + h * 8 + g;
                #pragma unroll
                for (int nj = 0; nj < 4; nj++) {
                    const int wcol = nj * 8 + k4 * 2;
                    if (wcol < VV)
                        y2s[c * 200 + t * 25 + wcol]     = __float2half(acc2[mi][nj][h * 2 + 0]);
                    if (wcol + 1 < VV)
                        y2s[c * 200 + t * 25 + wcol + 1] = __float2half(acc2[mi][nj][h * 2 + 1]);
                }
            }
        }
    }
    __syncthreads();

    // 4) BN partial stats from quantized y2 (first 256 threads: 32 c x 8 t)
    if (tid < 256) {
        const int cl = tid >> 3, tl = tid & 7;
        float s = 0.0f, s2 = 0.0f;
        #pragma unroll
        for (int v = 0; v < VV; v++) {
            float val = __half2float(y2s[cl * 200 + tl * 25 + v]);
            s += val; s2 += val * val;
        }
        s  += __shfl_down_sync(0xFFFFFFFFu, s,  4, 8);
        s2 += __shfl_down_sync(0xFFFFFFFFu, s2, 4, 8);
        s  += __shfl_down_sync(0xFFFFFFFFu, s,  2, 8);
        s2 += __shfl_down_sync(0xFFFFFFFFu, s2, 2, 8);
        s  += __shfl_down_sync(0xFFFFFFFFu, s,  1, 8);
        s2 += __shfl_down_sync(0xFFFFFFFFu, s2, 1, 8);
        if ((tid & 7) == 0) {
            atomicAdd(&g_sum2[slot * COUT + c0 + cl], s);
            atomicAdd(&g_sq2 [slot * COUT + c0 + cl], s2);
        }
    }

    // 5) coalesced copy y2s -> g_yo: 32 rows x 25 uint4 (8 halves) = full 200 cols
    {
        const size_t base = ((size_t)n * COUT + c0) * TVN + tvbase;   // half index, 16B-aligned
        const uint4* src = (const uint4*)y2s;                          // row stride 25 uint4
        uint4* dst = (uint4*)(g_yo + base);                            // row stride TVN/8 uint4
        #pragma unroll
        for (int p = 0; p < 3; p++) {
            int i = tid + p * NTHR;
            if (i < 800) {
                int row = i / 25, q4 = i % 25;
                dst[(size_t)row * (TVN / 8) + q4] = src[row * 25 + q4];
            }
        }
    }
}

// ---------------------------------------------------------------------------
// BN finalize + normalize + ReLU, one (n,c) slab per block.
// Each block computes its channel's scale/shift inline from the 16 stat slots.
// ---------------------------------------------------------------------------
__global__ __launch_bounds__(256) void bn_kernel(
    const float* __restrict__ gamma, const float* __restrict__ beta,
    float* __restrict__ out)
{
    const int bc = blockIdx.x;          // n*COUT + c
    const int c  = bc & (COUT - 1);

    float s = 0.0f, s2 = 0.0f;
    #pragma unroll
    for (int sl = 0; sl < NSLOT; sl++) {
        s  += g_sum2[sl * COUT + c];    // uniform address -> broadcast
        s2 += g_sq2 [sl * COUT + c];
    }
    const float inv_n = 1.0f / (float)NTV;
    const float mu  = s * inv_n;
    const float var = s2 * inv_n - mu * mu;
    const float rin = rsqrtf(var + BN_EPS);
    const float sc  = gamma[c] * rin;
    const float sh  = beta[c] - mu * sc;

    const uint4* in4 = (const uint4*)g_yo + (size_t)bc * (TVN / 8);
    float4* out4 = (float4*)out + (size_t)bc * (TVN / 4);

    for (int i = threadIdx.x; i < TVN / 8; i += 256) {
        uint4 raw = in4[i];
        float4 o0, o1;
        __half2 p = *(__half2*)&raw.x; float2 f = __half22float2(p);
        o0.x = fmaxf(f.x * sc + sh, 0.0f); o0.y = fmaxf(f.y * sc + sh, 0.0f);
        p = *(__half2*)&raw.y; f = __half22float2(p);
        o0.z = fmaxf(f.x * sc + sh, 0.0f); o0.w = fmaxf(f.y * sc + sh, 0.0f);
        p = *(__half2*)&raw.z; f = __half22float2(p);
        o1.x = fmaxf(f.x * sc + sh, 0.0f); o1.y = fmaxf(f.y * sc + sh, 0.0f);
        p = *(__half2*)&raw.w; f = __half22float2(p);
        o1.z = fmaxf(f.x * sc + sh, 0.0f); o1.w = fmaxf(f.y * sc + sh, 0.0f);
        out4[i * 2]     = o0;
        out4[i * 2 + 1] = o1;
    }
}

// ---------------------------------------------------------------------------
extern "C" void kernel_launch(void* const* d_in, const int* in_sizes, int n_in,
                              void* d_out, int out_size)
{
    const float* x     = (const float*)d_in[0];   // [32,256,128,25]
    const float* A     = (const float*)d_in[1];   // [3,25,25]
    const float* W     = (const float*)d_in[2];   // [768,256]
    const float* b     = (const float*)d_in[3];   // [768]
    const float* gamma = (const float*)d_in[4];   // [256]
    const float* beta  = (const float*)d_in[5];   // [256]

    cudaFuncSetAttribute(fused_kernel, cudaFuncAttributeMaxDynamicSharedMemorySize, DYN_BYTES);

    dim3 tg(100, 4, 32);
    transpose_kernel<<<tg, 256>>>(x, W);   // also converts W + zeroes BN stat slots

    dim3 grid(8, 512);   // M tiles fastest -> blocks sharing x tiles run adjacently
    fused_kernel<<<grid, NTHR, DYN_BYTES>>>(A, b);

    bn_kernel<<<NB * COUT, 256>>>(gamma, beta, (float*)d_out);
}